// round 2
// baseline (speedup 1.0000x reference)
#include <cuda_runtime.h>
#include <cstdint>

#define Td 8192
#define Hd 768
#define Fd 3072
#define Ed 8
#define KT 2
#define Pd (Td*KT)

// ---------------- scratch (static device globals; no allocation) ----------------
__device__ float g_h[(size_t)Pd * Fd];     // expert-hidden activations [pair, F]
__device__ float g_po[(size_t)Pd * Hd];    // per-pair expert output [pair, H]
__device__ int   g_tok[Pd];                // pair -> token
__device__ int   g_pos[Td*KT];             // (token,k) -> pair position
__device__ int   g_ti[Td*KT];              // (token,k) -> expert id
__device__ float g_tw[Td*KT];              // (token,k) -> routing weight
__device__ int   g_cnt[Ed];
__device__ int   g_off[Ed];
__device__ int   g_fill[Ed];

// ---------------- small helpers ----------------
__device__ __forceinline__ uint32_t f2tf(float f){
    uint32_t u; asm("cvt.rna.tf32.f32 %0, %1;" : "=r"(u) : "f"(f)); return u;
}
__device__ __forceinline__ void mma8(float* c, const uint32_t* a, const uint32_t* b){
    asm volatile(
        "mma.sync.aligned.m16n8k8.row.col.f32.tf32.tf32.f32 "
        "{%0,%1,%2,%3},{%4,%5,%6,%7},{%8,%9},{%0,%1,%2,%3};"
        : "+f"(c[0]), "+f"(c[1]), "+f"(c[2]), "+f"(c[3])
        : "r"(a[0]), "r"(a[1]), "r"(a[2]), "r"(a[3]), "r"(b[0]), "r"(b[1]));
}
__device__ __forceinline__ void cpa(uint32_t dst, const void* src, bool v){
    int sz = v ? 16 : 0;
    asm volatile("cp.async.cg.shared.global [%0], [%1], 16, %2;\n"
                 :: "r"(dst), "l"(src), "r"(sz));
}
__device__ __forceinline__ void cp_commit(){ asm volatile("cp.async.commit_group;\n"); }
template<int N> __device__ __forceinline__ void cp_wait(){
    asm volatile("cp.async.wait_group %0;\n" :: "n"(N));
}
__device__ __forceinline__ float gelu_f(float v){
    return 0.5f * v * (1.0f + erff(v * 0.70710678118654752f));
}

// ---------------- routing ----------------
__global__ void k_init(){
    int i = threadIdx.x;
    if (i < Ed){ g_cnt[i] = 0; g_fill[i] = 0; }
}

__global__ void k_router(const float* __restrict__ x, const float* __restrict__ Wr){
    __shared__ float sW[Ed*Hd];
    int tid = threadIdx.x;
    for (int i = tid; i < Ed*Hd; i += 256) sW[i] = Wr[i];
    __syncthreads();
    int warp = tid >> 5, lane = tid & 31;
    int t = blockIdx.x*8 + warp;
    const float* xp = x + (size_t)t*Hd;
    float xv[24];
    #pragma unroll
    for (int i = 0; i < 24; i++) xv[i] = xp[i*32 + lane];
    float lg[8];
    #pragma unroll
    for (int e = 0; e < 8; e++){
        float s = 0.f;
        #pragma unroll
        for (int i = 0; i < 24; i++) s += xv[i] * sW[e*Hd + i*32 + lane];
        #pragma unroll
        for (int o = 16; o; o >>= 1) s += __shfl_xor_sync(0xffffffffu, s, o);
        lg[e] = s;
    }
    if (lane == 0){
        int i0 = 0; float v0 = lg[0];
        #pragma unroll
        for (int e = 1; e < 8; e++) if (lg[e] > v0){ v0 = lg[e]; i0 = e; }
        int i1 = -1; float v1 = -1e30f;
        #pragma unroll
        for (int e = 0; e < 8; e++) if (e != i0 && lg[e] > v1){ v1 = lg[e]; i1 = e; }
        float e1 = expf(v1 - v0);      // v0 >= v1, stable 2-way softmax
        float s  = 1.f + e1;
        g_ti[t*2]   = i0;  g_ti[t*2+1] = i1;
        g_tw[t*2]   = 1.f/s; g_tw[t*2+1] = e1/s;
        atomicAdd(&g_cnt[i0], 1);
        atomicAdd(&g_cnt[i1], 1);
    }
}

__global__ void k_scan(){
    if (threadIdx.x == 0){
        int s = 0;
        #pragma unroll
        for (int e = 0; e < Ed; e++){ g_off[e] = s; s += g_cnt[e]; }
    }
}

__global__ void k_scatter(){
    int i = blockIdx.x*256 + threadIdx.x;
    if (i < Td*KT){
        int e = g_ti[i];
        int p = g_off[e] + atomicAdd(&g_fill[e], 1);
        g_tok[p] = i >> 1;
        g_pos[i] = p;
    }
}

// ---------------- GEMM1: h = gelu(gather(x) @ Wi[e]^T + bi[e]) ----------------
// Tile 128x128, BK=16, TF32 mma m16n8k8, 2-stage cp.async pipeline.
// smem rows padded to stride 20 floats -> conflict-free fragment loads.
__global__ __launch_bounds__(256) void k_gemm1(const float* __restrict__ x,
                                               const float* __restrict__ Wi,
                                               const float* __restrict__ bi){
    __shared__ float sm[4*2560];   // [A stage0|A stage1|B stage0|B stage1], 40KB
    const int e   = blockIdx.z;
    const int cnt = g_cnt[e];
    const int m0  = blockIdx.y * 128;
    if (m0 >= cnt) return;
    const int off = g_off[e];
    const int n0  = blockIdx.x * 128;
    const int tid = threadIdx.x;
    const int col = (tid & 3) * 4;

    const float* srcA[2]; bool vA[2];
    const float* srcB[2];
    uint32_t dstA[2], dstB[2];
    uint32_t sbase = (uint32_t)__cvta_generic_to_shared(sm);
    #pragma unroll
    for (int c = 0; c < 2; c++){
        int row = (tid >> 2) + c*64;
        int m   = m0 + row;
        bool v  = m < cnt;
        int token = v ? g_tok[off + m] : 0;
        srcA[c] = x + (size_t)token*Hd + col;
        vA[c]   = v;
        srcB[c] = Wi + ((size_t)e*Fd + (n0 + row))*Hd + col;
        dstA[c] = sbase + (uint32_t)((row*20 + col)*4);
        dstB[c] = sbase + (uint32_t)((5120 + row*20 + col)*4);
    }

    const int warp = tid >> 5;
    const int wm = warp >> 1, wn = warp & 1;         // 4x2 warp grid; warp tile 32x64
    const int gid = (tid & 31) >> 2, tg = tid & 3;

    float acc[2][8][4];
    #pragma unroll
    for (int a = 0; a < 2; a++)
        #pragma unroll
        for (int b = 0; b < 8; b++)
            #pragma unroll
            for (int c = 0; c < 4; c++) acc[a][b][c] = 0.f;

    const int KITER = Hd/16;   // 48
    #pragma unroll
    for (int c = 0; c < 2; c++){ cpa(dstA[c], srcA[c], vA[c]); cpa(dstB[c], srcB[c], true); }
    cp_commit();

    for (int it = 0; it < KITER; ++it){
        int st = it & 1;
        if (it + 1 < KITER){
            int k0 = (it + 1) * 16;
            uint32_t so = (uint32_t)((st ^ 1) * 2560 * 4);
            #pragma unroll
            for (int c = 0; c < 2; c++){
                cpa(dstA[c] + so, srcA[c] + k0, vA[c]);
                cpa(dstB[c] + so, srcB[c] + k0, true);
            }
            cp_commit();
            cp_wait<1>();
        } else {
            cp_wait<0>();
        }
        __syncthreads();
        const float* SA = sm + st*2560;
        const float* SB = sm + 5120 + st*2560;
        #pragma unroll
        for (int ks = 0; ks < 2; ks++){
            int kk = ks*8;
            uint32_t af[2][4], bf[8][2];
            #pragma unroll
            for (int mt = 0; mt < 2; mt++){
                int r = wm*32 + mt*16 + gid;
                af[mt][0] = f2tf(SA[ r    *20 + kk + tg    ]);
                af[mt][1] = f2tf(SA[(r+8) *20 + kk + tg    ]);
                af[mt][2] = f2tf(SA[ r    *20 + kk + tg + 4]);
                af[mt][3] = f2tf(SA[(r+8) *20 + kk + tg + 4]);
            }
            #pragma unroll
            for (int nt = 0; nt < 8; nt++){
                int rn = wn*64 + nt*8 + gid;
                bf[nt][0] = f2tf(SB[rn*20 + kk + tg    ]);
                bf[nt][1] = f2tf(SB[rn*20 + kk + tg + 4]);
            }
            #pragma unroll
            for (int mt = 0; mt < 2; mt++)
                #pragma unroll
                for (int nt = 0; nt < 8; nt++)
                    mma8(acc[mt][nt], af[mt], bf[nt]);
        }
        __syncthreads();
    }

    #pragma unroll
    for (int mt = 0; mt < 2; mt++){
        int ml = wm*32 + mt*16 + gid;
        #pragma unroll
        for (int nt = 0; nt < 8; nt++){
            int n = n0 + wn*64 + nt*8 + tg*2;
            float b0 = bi[e*Fd + n], b1 = bi[e*Fd + n + 1];
            int m = m0 + ml;
            if (m < cnt){
                size_t o = (size_t)(off + m)*Fd + n;
                g_h[o]     = gelu_f(acc[mt][nt][0] + b0);
                g_h[o + 1] = gelu_f(acc[mt][nt][1] + b1);
            }
            if (m + 8 < cnt){
                size_t o = (size_t)(off + m + 8)*Fd + n;
                g_h[o]     = gelu_f(acc[mt][nt][2] + b0);
                g_h[o + 1] = gelu_f(acc[mt][nt][3] + b1);
            }
        }
    }
}

// ---------------- GEMM2: po = h @ Wo[e]^T + bo[e] ----------------
__global__ __launch_bounds__(256) void k_gemm2(const float* __restrict__ Wo,
                                               const float* __restrict__ bo){
    __shared__ float sm[4*2560];
    const int e   = blockIdx.z;
    const int cnt = g_cnt[e];
    const int m0  = blockIdx.y * 128;
    if (m0 >= cnt) return;
    const int off = g_off[e];
    const int n0  = blockIdx.x * 128;
    const int tid = threadIdx.x;
    const int col = (tid & 3) * 4;

    const float* srcA[2]; bool vA[2];
    const float* srcB[2];
    uint32_t dstA[2], dstB[2];
    uint32_t sbase = (uint32_t)__cvta_generic_to_shared(sm);
    #pragma unroll
    for (int c = 0; c < 2; c++){
        int row = (tid >> 2) + c*64;
        int m   = m0 + row;
        bool v  = m < cnt;
        size_t ai = v ? (size_t)(off + m)*Fd : 0;
        srcA[c] = g_h + ai + col;
        vA[c]   = v;
        srcB[c] = Wo + ((size_t)e*Hd + (n0 + row))*Fd + col;
        dstA[c] = sbase + (uint32_t)((row*20 + col)*4);
        dstB[c] = sbase + (uint32_t)((5120 + row*20 + col)*4);
    }

    const int warp = tid >> 5;
    const int wm = warp >> 1, wn = warp & 1;
    const int gid = (tid & 31) >> 2, tg = tid & 3;

    float acc[2][8][4];
    #pragma unroll
    for (int a = 0; a < 2; a++)
        #pragma unroll
        for (int b = 0; b < 8; b++)
            #pragma unroll
            for (int c = 0; c < 4; c++) acc[a][b][c] = 0.f;

    const int KITER = Fd/16;   // 192
    #pragma unroll
    for (int c = 0; c < 2; c++){ cpa(dstA[c], srcA[c], vA[c]); cpa(dstB[c], srcB[c], true); }
    cp_commit();

    for (int it = 0; it < KITER; ++it){
        int st = it & 1;
        if (it + 1 < KITER){
            int k0 = (it + 1) * 16;
            uint32_t so = (uint32_t)((st ^ 1) * 2560 * 4);
            #pragma unroll
            for (int c = 0; c < 2; c++){
                cpa(dstA[c] + so, srcA[c] + k0, vA[c]);
                cpa(dstB[c] + so, srcB[c] + k0, true);
            }
            cp_commit();
            cp_wait<1>();
        } else {
            cp_wait<0>();
        }
        __syncthreads();
        const float* SA = sm + st*2560;
        const float* SB = sm + 5120 + st*2560;
        #pragma unroll
        for (int ks = 0; ks < 2; ks++){
            int kk = ks*8;
            uint32_t af[2][4], bf[8][2];
            #pragma unroll
            for (int mt = 0; mt < 2; mt++){
                int r = wm*32 + mt*16 + gid;
                af[mt][0] = f2tf(SA[ r    *20 + kk + tg    ]);
                af[mt][1] = f2tf(SA[(r+8) *20 + kk + tg    ]);
                af[mt][2] = f2tf(SA[ r    *20 + kk + tg + 4]);
                af[mt][3] = f2tf(SA[(r+8) *20 + kk + tg + 4]);
            }
            #pragma unroll
            for (int nt = 0; nt < 8; nt++){
                int rn = wn*64 + nt*8 + gid;
                bf[nt][0] = f2tf(SB[rn*20 + kk + tg    ]);
                bf[nt][1] = f2tf(SB[rn*20 + kk + tg + 4]);
            }
            #pragma unroll
            for (int mt = 0; mt < 2; mt++)
                #pragma unroll
                for (int nt = 0; nt < 8; nt++)
                    mma8(acc[mt][nt], af[mt], bf[nt]);
        }
        __syncthreads();
    }

    #pragma unroll
    for (int mt = 0; mt < 2; mt++){
        int ml = wm*32 + mt*16 + gid;
        #pragma unroll
        for (int nt = 0; nt < 8; nt++){
            int n = n0 + wn*64 + nt*8 + tg*2;
            float b0 = bo[e*Hd + n], b1 = bo[e*Hd + n + 1];
            int m = m0 + ml;
            if (m < cnt){
                size_t o = (size_t)(off + m)*Hd + n;
                g_po[o]     = acc[mt][nt][0] + b0;
                g_po[o + 1] = acc[mt][nt][1] + b1;
            }
            if (m + 8 < cnt){
                size_t o = (size_t)(off + m + 8)*Hd + n;
                g_po[o]     = acc[mt][nt][2] + b0;
                g_po[o + 1] = acc[mt][nt][3] + b1;
            }
        }
    }
}

// ---------------- combine: out[t] = w0*po[p0] + w1*po[p1] ----------------
__global__ void k_combine(float* __restrict__ out){
    int t = blockIdx.x;
    int j = threadIdx.x * 4;
    int p0 = g_pos[t*2], p1 = g_pos[t*2+1];
    float w0 = g_tw[t*2], w1 = g_tw[t*2+1];
    float4 a = *(const float4*)(g_po + (size_t)p0*Hd + j);
    float4 b = *(const float4*)(g_po + (size_t)p1*Hd + j);
    float4 r;
    r.x = w0*a.x + w1*b.x;
    r.y = w0*a.y + w1*b.y;
    r.z = w0*a.z + w1*b.z;
    r.w = w0*a.w + w1*b.w;
    *(float4*)(out + (size_t)t*Hd + j) = r;
}

// ---------------- launch ----------------
extern "C" void kernel_launch(void* const* d_in, const int* in_sizes, int n_in,
                              void* d_out, int out_size){
    const float* x  = (const float*)d_in[0];
    const float* Wr = (const float*)d_in[1];
    const float* Wi = (const float*)d_in[2];
    const float* bi = (const float*)d_in[3];
    const float* Wo = (const float*)d_in[4];
    const float* bo = (const float*)d_in[5];
    float* out = (float*)d_out;

    k_init<<<1, 32>>>();
    k_router<<<Td/8, 256>>>(x, Wr);
    k_scan<<<1, 32>>>();
    k_scatter<<<(Td*KT + 255)/256, 256>>>();
    k_gemm1<<<dim3(Fd/128, Td/128, Ed), 256>>>(x, Wi, bi);
    k_gemm2<<<dim3(Hd/128, Td/128, Ed), 256>>>(Wo, bo);
    k_combine<<<Td, 192>>>(out);
}

// round 3
// speedup vs baseline: 1.0009x; 1.0009x over previous
#include <cuda_runtime.h>
#include <cstdint>

#define Td 8192
#define Hd 768
#define Fd 3072
#define Ed 8
#define KT 2
#define Pd (Td*KT)

// ---------------- scratch (static device globals; no allocation) ----------------
__device__ float g_h[(size_t)Pd * Fd];     // expert-hidden activations [pair, F]
__device__ float g_po[(size_t)Pd * Hd];    // per-pair expert output [pair, H]
__device__ int   g_tok[Pd];                // pair -> token
__device__ int   g_pos[Td*KT];             // (token,k) -> pair position
__device__ int   g_ti[Td*KT];              // (token,k) -> expert id
__device__ float g_tw[Td*KT];              // (token,k) -> routing weight
__device__ int   g_cnt[Ed];
__device__ int   g_off[Ed];
__device__ int   g_fill[Ed];

// ---------------- small helpers ----------------
__device__ __forceinline__ uint32_t f2tf(float f){
    uint32_t u; asm("cvt.rna.tf32.f32 %0, %1;" : "=r"(u) : "f"(f)); return u;
}
__device__ __forceinline__ void mma8(float* c, const uint32_t* a, const uint32_t* b){
    asm volatile(
        "mma.sync.aligned.m16n8k8.row.col.f32.tf32.tf32.f32 "
        "{%0,%1,%2,%3},{%4,%5,%6,%7},{%8,%9},{%0,%1,%2,%3};"
        : "+f"(c[0]), "+f"(c[1]), "+f"(c[2]), "+f"(c[3])
        : "r"(a[0]), "r"(a[1]), "r"(a[2]), "r"(a[3]), "r"(b[0]), "r"(b[1]));
}
__device__ __forceinline__ void cpa(uint32_t dst, const void* src, bool v){
    int sz = v ? 16 : 0;
    asm volatile("cp.async.cg.shared.global [%0], [%1], 16, %2;\n"
                 :: "r"(dst), "l"(src), "r"(sz));
}
__device__ __forceinline__ void cp_commit(){ asm volatile("cp.async.commit_group;\n"); }
template<int N> __device__ __forceinline__ void cp_wait(){
    asm volatile("cp.async.wait_group %0;\n" :: "n"(N));
}
__device__ __forceinline__ float gelu_f(float v){
    return 0.5f * v * (1.0f + erff(v * 0.70710678118654752f));
}

// ---------------- routing ----------------
__global__ void k_init(){
    int i = threadIdx.x;
    if (i < Ed){ g_cnt[i] = 0; g_fill[i] = 0; }
}

__global__ void k_router(const float* __restrict__ x, const float* __restrict__ Wr){
    __shared__ float sW[Ed*Hd];
    int tid = threadIdx.x;
    for (int i = tid; i < Ed*Hd; i += 256) sW[i] = Wr[i];
    __syncthreads();
    int warp = tid >> 5, lane = tid & 31;
    int t = blockIdx.x*8 + warp;
    const float* xp = x + (size_t)t*Hd;
    float xv[24];
    #pragma unroll
    for (int i = 0; i < 24; i++) xv[i] = xp[i*32 + lane];
    float lg[8];
    #pragma unroll
    for (int e = 0; e < 8; e++){
        float s = 0.f;
        #pragma unroll
        for (int i = 0; i < 24; i++) s += xv[i] * sW[e*Hd + i*32 + lane];
        #pragma unroll
        for (int o = 16; o; o >>= 1) s += __shfl_xor_sync(0xffffffffu, s, o);
        lg[e] = s;
    }
    if (lane == 0){
        int i0 = 0; float v0 = lg[0];
        #pragma unroll
        for (int e = 1; e < 8; e++) if (lg[e] > v0){ v0 = lg[e]; i0 = e; }
        int i1 = -1; float v1 = -1e30f;
        #pragma unroll
        for (int e = 0; e < 8; e++) if (e != i0 && lg[e] > v1){ v1 = lg[e]; i1 = e; }
        float e1 = expf(v1 - v0);      // v0 >= v1, stable 2-way softmax
        float s  = 1.f + e1;
        g_ti[t*2]   = i0;  g_ti[t*2+1] = i1;
        g_tw[t*2]   = 1.f/s; g_tw[t*2+1] = e1/s;
        atomicAdd(&g_cnt[i0], 1);
        atomicAdd(&g_cnt[i1], 1);
    }
}

__global__ void k_scan(){
    if (threadIdx.x == 0){
        int s = 0;
        #pragma unroll
        for (int e = 0; e < Ed; e++){ g_off[e] = s; s += g_cnt[e]; }
    }
}

__global__ void k_scatter(){
    int i = blockIdx.x*256 + threadIdx.x;
    if (i < Td*KT){
        int e = g_ti[i];
        int p = g_off[e] + atomicAdd(&g_fill[e], 1);
        g_tok[p] = i >> 1;
        g_pos[i] = p;
    }
}

// ---------------- GEMM1: h = gelu(gather(x) @ Wi[e]^T + bi[e]) ----------------
// Tile 128x128, BK=16, TF32 mma m16n8k8, 2-stage cp.async pipeline.
// smem rows padded to stride 20 floats -> conflict-free fragment loads.
__global__ __launch_bounds__(256) void k_gemm1(const float* __restrict__ x,
                                               const float* __restrict__ Wi,
                                               const float* __restrict__ bi){
    __shared__ float sm[4*2560];   // [A stage0|A stage1|B stage0|B stage1], 40KB
    const int e   = blockIdx.z;
    const int cnt = g_cnt[e];
    const int m0  = blockIdx.y * 128;
    if (m0 >= cnt) return;
    const int off = g_off[e];
    const int n0  = blockIdx.x * 128;
    const int tid = threadIdx.x;
    const int col = (tid & 3) * 4;

    const float* srcA[2]; bool vA[2];
    const float* srcB[2];
    uint32_t dstA[2], dstB[2];
    uint32_t sbase = (uint32_t)__cvta_generic_to_shared(sm);
    #pragma unroll
    for (int c = 0; c < 2; c++){
        int row = (tid >> 2) + c*64;
        int m   = m0 + row;
        bool v  = m < cnt;
        int token = v ? g_tok[off + m] : 0;
        srcA[c] = x + (size_t)token*Hd + col;
        vA[c]   = v;
        srcB[c] = Wi + ((size_t)e*Fd + (n0 + row))*Hd + col;
        dstA[c] = sbase + (uint32_t)((row*20 + col)*4);
        dstB[c] = sbase + (uint32_t)((5120 + row*20 + col)*4);
    }

    const int warp = tid >> 5;
    const int wm = warp >> 1, wn = warp & 1;         // 4x2 warp grid; warp tile 32x64
    const int gid = (tid & 31) >> 2, tg = tid & 3;

    float acc[2][8][4];
    #pragma unroll
    for (int a = 0; a < 2; a++)
        #pragma unroll
        for (int b = 0; b < 8; b++)
            #pragma unroll
            for (int c = 0; c < 4; c++) acc[a][b][c] = 0.f;

    const int KITER = Hd/16;   // 48
    #pragma unroll
    for (int c = 0; c < 2; c++){ cpa(dstA[c], srcA[c], vA[c]); cpa(dstB[c], srcB[c], true); }
    cp_commit();

    for (int it = 0; it < KITER; ++it){
        int st = it & 1;
        if (it + 1 < KITER){
            int k0 = (it + 1) * 16;
            uint32_t so = (uint32_t)((st ^ 1) * 2560 * 4);
            #pragma unroll
            for (int c = 0; c < 2; c++){
                cpa(dstA[c] + so, srcA[c] + k0, vA[c]);
                cpa(dstB[c] + so, srcB[c] + k0, true);
            }
            cp_commit();
            cp_wait<1>();
        } else {
            cp_wait<0>();
        }
        __syncthreads();
        const float* SA = sm + st*2560;
        const float* SB = sm + 5120 + st*2560;
        #pragma unroll
        for (int ks = 0; ks < 2; ks++){
            int kk = ks*8;
            uint32_t af[2][4], bf[8][2];
            #pragma unroll
            for (int mt = 0; mt < 2; mt++){
                int r = wm*32 + mt*16 + gid;
                af[mt][0] = f2tf(SA[ r    *20 + kk + tg    ]);
                af[mt][1] = f2tf(SA[(r+8) *20 + kk + tg    ]);
                af[mt][2] = f2tf(SA[ r    *20 + kk + tg + 4]);
                af[mt][3] = f2tf(SA[(r+8) *20 + kk + tg + 4]);
            }
            #pragma unroll
            for (int nt = 0; nt < 8; nt++){
                int rn = wn*64 + nt*8 + gid;
                bf[nt][0] = f2tf(SB[rn*20 + kk + tg    ]);
                bf[nt][1] = f2tf(SB[rn*20 + kk + tg + 4]);
            }
            #pragma unroll
            for (int mt = 0; mt < 2; mt++)
                #pragma unroll
                for (int nt = 0; nt < 8; nt++)
                    mma8(acc[mt][nt], af[mt], bf[nt]);
        }
        __syncthreads();
    }

    #pragma unroll
    for (int mt = 0; mt < 2; mt++){
        int ml = wm*32 + mt*16 + gid;
        #pragma unroll
        for (int nt = 0; nt < 8; nt++){
            int n = n0 + wn*64 + nt*8 + tg*2;
            float b0 = bi[e*Fd + n], b1 = bi[e*Fd + n + 1];
            int m = m0 + ml;
            if (m < cnt){
                size_t o = (size_t)(off + m)*Fd + n;
                g_h[o]     = gelu_f(acc[mt][nt][0] + b0);
                g_h[o + 1] = gelu_f(acc[mt][nt][1] + b1);
            }
            if (m + 8 < cnt){
                size_t o = (size_t)(off + m + 8)*Fd + n;
                g_h[o]     = gelu_f(acc[mt][nt][2] + b0);
                g_h[o + 1] = gelu_f(acc[mt][nt][3] + b1);
            }
        }
    }
}

// ---------------- GEMM2: po = h @ Wo[e]^T + bo[e] ----------------
__global__ __launch_bounds__(256) void k_gemm2(const float* __restrict__ Wo,
                                               const float* __restrict__ bo){
    __shared__ float sm[4*2560];
    const int e   = blockIdx.z;
    const int cnt = g_cnt[e];
    const int m0  = blockIdx.y * 128;
    if (m0 >= cnt) return;
    const int off = g_off[e];
    const int n0  = blockIdx.x * 128;
    const int tid = threadIdx.x;
    const int col = (tid & 3) * 4;

    const float* srcA[2]; bool vA[2];
    const float* srcB[2];
    uint32_t dstA[2], dstB[2];
    uint32_t sbase = (uint32_t)__cvta_generic_to_shared(sm);
    #pragma unroll
    for (int c = 0; c < 2; c++){
        int row = (tid >> 2) + c*64;
        int m   = m0 + row;
        bool v  = m < cnt;
        size_t ai = v ? (size_t)(off + m)*Fd : 0;
        srcA[c] = g_h + ai + col;
        vA[c]   = v;
        srcB[c] = Wo + ((size_t)e*Hd + (n0 + row))*Fd + col;
        dstA[c] = sbase + (uint32_t)((row*20 + col)*4);
        dstB[c] = sbase + (uint32_t)((5120 + row*20 + col)*4);
    }

    const int warp = tid >> 5;
    const int wm = warp >> 1, wn = warp & 1;
    const int gid = (tid & 31) >> 2, tg = tid & 3;

    float acc[2][8][4];
    #pragma unroll
    for (int a = 0; a < 2; a++)
        #pragma unroll
        for (int b = 0; b < 8; b++)
            #pragma unroll
            for (int c = 0; c < 4; c++) acc[a][b][c] = 0.f;

    const int KITER = Fd/16;   // 192
    #pragma unroll
    for (int c = 0; c < 2; c++){ cpa(dstA[c], srcA[c], vA[c]); cpa(dstB[c], srcB[c], true); }
    cp_commit();

    for (int it = 0; it < KITER; ++it){
        int st = it & 1;
        if (it + 1 < KITER){
            int k0 = (it + 1) * 16;
            uint32_t so = (uint32_t)((st ^ 1) * 2560 * 4);
            #pragma unroll
            for (int c = 0; c < 2; c++){
                cpa(dstA[c] + so, srcA[c] + k0, vA[c]);
                cpa(dstB[c] + so, srcB[c] + k0, true);
            }
            cp_commit();
            cp_wait<1>();
        } else {
            cp_wait<0>();
        }
        __syncthreads();
        const float* SA = sm + st*2560;
        const float* SB = sm + 5120 + st*2560;
        #pragma unroll
        for (int ks = 0; ks < 2; ks++){
            int kk = ks*8;
            uint32_t af[2][4], bf[8][2];
            #pragma unroll
            for (int mt = 0; mt < 2; mt++){
                int r = wm*32 + mt*16 + gid;
                af[mt][0] = f2tf(SA[ r    *20 + kk + tg    ]);
                af[mt][1] = f2tf(SA[(r+8) *20 + kk + tg    ]);
                af[mt][2] = f2tf(SA[ r    *20 + kk + tg + 4]);
                af[mt][3] = f2tf(SA[(r+8) *20 + kk + tg + 4]);
            }
            #pragma unroll
            for (int nt = 0; nt < 8; nt++){
                int rn = wn*64 + nt*8 + gid;
                bf[nt][0] = f2tf(SB[rn*20 + kk + tg    ]);
                bf[nt][1] = f2tf(SB[rn*20 + kk + tg + 4]);
            }
            #pragma unroll
            for (int mt = 0; mt < 2; mt++)
                #pragma unroll
                for (int nt = 0; nt < 8; nt++)
                    mma8(acc[mt][nt], af[mt], bf[nt]);
        }
        __syncthreads();
    }

    #pragma unroll
    for (int mt = 0; mt < 2; mt++){
        int ml = wm*32 + mt*16 + gid;
        #pragma unroll
        for (int nt = 0; nt < 8; nt++){
            int n = n0 + wn*64 + nt*8 + tg*2;
            float b0 = bo[e*Hd + n], b1 = bo[e*Hd + n + 1];
            int m = m0 + ml;
            if (m < cnt){
                size_t o = (size_t)(off + m)*Hd + n;
                g_po[o]     = acc[mt][nt][0] + b0;
                g_po[o + 1] = acc[mt][nt][1] + b1;
            }
            if (m + 8 < cnt){
                size_t o = (size_t)(off + m + 8)*Hd + n;
                g_po[o]     = acc[mt][nt][2] + b0;
                g_po[o + 1] = acc[mt][nt][3] + b1;
            }
        }
    }
}

// ---------------- combine: out[t] = w0*po[p0] + w1*po[p1] ----------------
__global__ void k_combine(float* __restrict__ out){
    int t = blockIdx.x;
    int j = threadIdx.x * 4;
    int p0 = g_pos[t*2], p1 = g_pos[t*2+1];
    float w0 = g_tw[t*2], w1 = g_tw[t*2+1];
    float4 a = *(const float4*)(g_po + (size_t)p0*Hd + j);
    float4 b = *(const float4*)(g_po + (size_t)p1*Hd + j);
    float4 r;
    r.x = w0*a.x + w1*b.x;
    r.y = w0*a.y + w1*b.y;
    r.z = w0*a.z + w1*b.z;
    r.w = w0*a.w + w1*b.w;
    *(float4*)(out + (size_t)t*Hd + j) = r;
}

// ---------------- launch ----------------
extern "C" void kernel_launch(void* const* d_in, const int* in_sizes, int n_in,
                              void* d_out, int out_size){
    const float* x  = (const float*)d_in[0];
    const float* Wr = (const float*)d_in[1];
    const float* Wi = (const float*)d_in[2];
    const float* bi = (const float*)d_in[3];
    const float* Wo = (const float*)d_in[4];
    const float* bo = (const float*)d_in[5];
    float* out = (float*)d_out;

    k_init<<<1, 32>>>();
    k_router<<<Td/8, 256>>>(x, Wr);
    k_scan<<<1, 32>>>();
    k_scatter<<<(Td*KT + 255)/256, 256>>>();
    k_gemm1<<<dim3(Fd/128, Td/128, Ed), 256>>>(x, Wi, bi);
    k_gemm2<<<dim3(Hd/128, Td/128, Ed), 256>>>(Wo, bo);
    k_combine<<<Td, 192>>>(out);
}